// round 3
// baseline (speedup 1.0000x reference)
#include <cuda_runtime.h>

#define C_CH   256
#define Hf     100
#define Wf     100
#define HWf    (Hf * Wf)
#define GRIDP  8
#define OUTP   7
#define HALF_C 128

// NHWC scratch: [B][H][W][C], B<=2. 16B-aligned for vector LDG.
__device__ __align__(16) float g_featT[2 * HWf * C_CH];

// ---------------------------------------------------------------------------
// Kernel 1: NCHW -> NHWC transpose (per batch, [C=256, HW=10000] -> [HW, C])
// ---------------------------------------------------------------------------
__global__ void nchw_to_nhwc_kernel(const float* __restrict__ in) {
    __shared__ float tile[32][33];
    const int b   = blockIdx.z;
    const int hw0 = blockIdx.x * 32;
    const int c0  = blockIdx.y * 32;

    const float* inb = in + (size_t)b * C_CH * HWf;
    #pragma unroll
    for (int j = 0; j < 4; ++j) {
        int c  = c0 + threadIdx.y + j * 8;
        int hw = hw0 + threadIdx.x;
        if (hw < HWf)
            tile[threadIdx.y + j * 8][threadIdx.x] = inb[(size_t)c * HWf + hw];
    }
    __syncthreads();

    float* outb = g_featT + (size_t)b * HWf * C_CH;
    #pragma unroll
    for (int j = 0; j < 4; ++j) {
        int hw = hw0 + threadIdx.y + j * 8;
        int c  = c0 + threadIdx.x;
        if (hw < HWf)
            outb[(size_t)hw * C_CH + c] = tile[threadIdx.x][threadIdx.y + j * 8];
    }
}

// ---------------------------------------------------------------------------
// Kernel 2: RoIAlign (8x8 grid) + 2x2/s1 avg pool.
// block = (roi n, channel-half of 128). 64 threads; thread owns a channel
// pair (float2 / LDG.64). Pooled 7x7 accumulates ENTIRELY in registers
// (49 float2) so no smem traffic sits inside the mainloop; a small 6.3KB
// rotating smem buffer is used only at the end, in 4 flush rounds, each a
// dense contiguous float4 stream. smem/block drops 25KB -> 6.3KB, lifting
// blocks/SM from 9 to ~20 (occupancy ~23% -> ~60%).
// ---------------------------------------------------------------------------
__global__ __launch_bounds__(64) void roi_align_avg_kernel(
    const float* __restrict__ rois,
    const float* __restrict__ scale_p,
    float* __restrict__ out)
{
    __shared__ __align__(16) float s_out[32 * OUTP * OUTP];   // 6272 B

    const int n    = blockIdx.x;
    const int half = blockIdx.y;
    const int tid  = threadIdx.x;                   // 0..63
    const int c    = half * HALF_C + tid * 2;       // channel pair base

    const float scale = scale_p[0];
    const float* r = rois + (size_t)n * 5;
    const int   b  = (int)r[0];
    const float x1 = r[1] * scale;
    const float y1 = r[2] * scale;
    const float x2 = r[3] * scale;
    const float y2 = r[4] * scale;

    const float bw = fmaxf(x2 - x1, 0.0f) / (float)(GRIDP - 1);
    const float bh = fmaxf(y2 - y1, 0.0f) / (float)(GRIDP - 1);

    int   x0i[GRIDP];
    float lx[GRIDP];
    float vxm[GRIDP];
    #pragma unroll
    for (int g = 0; g < GRIDP; ++g) {
        float xs = x1 + (float)g * bw;
        vxm[g]   = (xs >= 0.0f && xs < (float)Wf) ? 1.0f : 0.0f;
        float xf = fminf(fmaxf(floorf(xs), 0.0f), (float)(Wf - 2));
        x0i[g]   = (int)xf;
        lx[g]    = xs - xf;
    }

    const float* fb = g_featT + (size_t)b * HWf * C_CH + c;

    float2 pooled[OUTP][OUTP];
    float2 prev[GRIDP];

    #pragma unroll
    for (int gy = 0; gy < GRIDP; ++gy) {
        float ys  = y1 + (float)gy * bh;
        float vym = (ys >= 0.0f && ys < (float)Hf) ? 1.0f : 0.0f;
        float yf  = fminf(fmaxf(floorf(ys), 0.0f), (float)(Hf - 2));
        int   y0  = (int)yf;
        float ly  = ys - yf;

        const float* row0 = fb + (size_t)y0 * (Wf * C_CH);

        // Batch all 32 tap loads of this sample row first (max MLP).
        float2 v00[GRIDP], v01[GRIDP], v10[GRIDP], v11[GRIDP];
        #pragma unroll
        for (int gx = 0; gx < GRIDP; ++gx) {
            const float* p = row0 + x0i[gx] * C_CH;
            v00[gx] = *(const float2*)(p);
            v01[gx] = *(const float2*)(p + C_CH);
            v10[gx] = *(const float2*)(p + Wf * C_CH);
            v11[gx] = *(const float2*)(p + Wf * C_CH + C_CH);
        }

        float2 cur[GRIDP];
        #pragma unroll
        for (int gx = 0; gx < GRIDP; ++gx) {
            float m = vym * vxm[gx];
            float tx, bx;
            tx = v00[gx].x + lx[gx] * (v01[gx].x - v00[gx].x);
            bx = v10[gx].x + lx[gx] * (v11[gx].x - v10[gx].x);
            cur[gx].x = (tx + ly * (bx - tx)) * m;
            tx = v00[gx].y + lx[gx] * (v01[gx].y - v00[gx].y);
            bx = v10[gx].y + lx[gx] * (v11[gx].y - v10[gx].y);
            cur[gx].y = (tx + ly * (bx - tx)) * m;
        }

        if (gy > 0) {
            #pragma unroll
            for (int ox = 0; ox < OUTP; ++ox) {
                pooled[gy - 1][ox].x =
                    0.25f * (prev[ox].x + prev[ox + 1].x + cur[ox].x + cur[ox + 1].x);
                pooled[gy - 1][ox].y =
                    0.25f * (prev[ox].y + prev[ox + 1].y + cur[ox].y + cur[ox + 1].y);
            }
        }
        #pragma unroll
        for (int i = 0; i < GRIDP; ++i) prev[i] = cur[i];
    }

    // ---- Flush: 4 rounds x 32 channels through the small smem buffer ----
    float4* o4_base = (float4*)(out + (size_t)n * (C_CH * OUTP * OUTP)
                                     + (size_t)half * (HALF_C * OUTP * OUTP));
    #pragma unroll
    for (int rr = 0; rr < 4; ++rr) {
        __syncthreads();                       // buffer free from prior round
        if ((tid >> 4) == rr) {
            int u = tid & 15;                  // 0..15 -> local ch 32rr+2u, +1
            #pragma unroll
            for (int oy = 0; oy < OUTP; ++oy)
                #pragma unroll
                for (int ox = 0; ox < OUTP; ++ox) {
                    int k = oy * OUTP + ox;
                    s_out[(2 * u)     * (OUTP * OUTP) + k] = pooled[oy][ox].x;
                    s_out[(2 * u + 1) * (OUTP * OUTP) + k] = pooled[oy][ox].y;
                }
        }
        __syncthreads();
        const float4* s4 = (const float4*)s_out;
        float4*       o4 = o4_base + rr * (32 * OUTP * OUTP / 4);
        #pragma unroll
        for (int i = 0; i < (32 * OUTP * OUTP / 4); i += 64)
            if (i + tid < (32 * OUTP * OUTP / 4))
                o4[i + tid] = s4[i + tid];
    }
}

extern "C" void kernel_launch(void* const* d_in, const int* in_sizes, int n_in,
                              void* d_out, int out_size) {
    const float* feat  = (const float*)d_in[0];
    const float* rois  = (const float*)d_in[1];
    const float* scale = (const float*)d_in[2];
    float*       out   = (float*)d_out;

    const int B = in_sizes[0] / (C_CH * HWf);   // 2
    const int N = in_sizes[1] / 5;              // 2048

    dim3 tb(32, 8);
    dim3 tg((HWf + 31) / 32, C_CH / 32, B);
    nchw_to_nhwc_kernel<<<tg, tb>>>(feat);

    dim3 rg(N, C_CH / HALF_C);
    roi_align_avg_kernel<<<rg, 64>>>(rois, scale, out);
}